// round 1
// baseline (speedup 1.0000x reference)
#include <cuda_runtime.h>
#include <cuda_fp16.h>
#include <mma.h>

using namespace nvcuda;

#define N_ROWS 8192
#define K_FEAT 512

static __device__ __half g_feats[(size_t)N_ROWS * K_FEAT];           // 8 MB
static __device__ float  g_S32[(size_t)N_ROWS * N_ROWS];             // 256 MB raw similarity
static __device__ __half g_Sh[(size_t)N_ROWS * N_ROWS];              // 128 MB thresholded fp16
static __device__ float  g_rowsum[N_ROWS];
static __device__ float  g_dinv[N_ROWS];
static __device__ float  g_dd[N_ROWS];
static __device__ __half g_Xs[(size_t)N_ROWS * K_FEAT];              // 8 MB
static __device__ float  g_Y[(size_t)N_ROWS * K_FEAT];               // 16 MB

// ---------------------------------------------------------------------------
// 1. Row L2-normalize X -> fp16 feats
// ---------------------------------------------------------------------------
__global__ void normalize_kernel(const float* __restrict__ X) {
    int row = blockIdx.x;
    const float* x = X + (size_t)row * K_FEAT;
    float s = 0.f;
    for (int k = threadIdx.x; k < K_FEAT; k += 128) {
        float v = x[k];
        s += v * v;
    }
    __shared__ float red[4];
    #pragma unroll
    for (int o = 16; o > 0; o >>= 1) s += __shfl_xor_sync(0xffffffff, s, o);
    if ((threadIdx.x & 31) == 0) red[threadIdx.x >> 5] = s;
    __syncthreads();
    float tot = red[0] + red[1] + red[2] + red[3];
    float inv = 1.0f / fmaxf(sqrtf(tot), 1e-12f);
    __half* f = g_feats + (size_t)row * K_FEAT;
    for (int k = threadIdx.x; k < K_FEAT; k += 128) {
        f[k] = __float2half(x[k] * inv);
    }
}

// ---------------------------------------------------------------------------
// 2. GEMM1: S32 = feats @ feats^T   (fp16 in, fp32 out)
//    128x128 block tile, BK=32, 8 warps each computing 64x32
// ---------------------------------------------------------------------------
#define BM 128
#define BN 128
#define BK 32
#define LDA 40   // padded leading dim in halves (80B rows: 16B aligned, conflict-reducing)

__global__ __launch_bounds__(256) void gemm1_kernel() {
    __shared__ __half As[BM][LDA];
    __shared__ __half Bs[BN][LDA];

    const int row0 = blockIdx.y * BM;
    const int col0 = blockIdx.x * BN;
    const int tid  = threadIdx.x;
    const int wid  = tid >> 5;
    const int warp_m = wid >> 2;   // 0..1  (64 rows each)
    const int warp_n = wid & 3;    // 0..3  (32 cols each)

    wmma::fragment<wmma::accumulator, 16, 16, 16, float> acc[4][2];
    #pragma unroll
    for (int mi = 0; mi < 4; mi++)
        #pragma unroll
        for (int ni = 0; ni < 2; ni++)
            wmma::fill_fragment(acc[mi][ni], 0.0f);

    for (int k0 = 0; k0 < K_FEAT; k0 += BK) {
        __syncthreads();
        #pragma unroll
        for (int it = 0; it < 2; it++) {
            int idx = tid + it * 256;
            int r = idx >> 2, c4 = idx & 3;
            *(float4*)&As[r][c4 * 8] =
                *(const float4*)&g_feats[(size_t)(row0 + r) * K_FEAT + k0 + c4 * 8];
            *(float4*)&Bs[r][c4 * 8] =
                *(const float4*)&g_feats[(size_t)(col0 + r) * K_FEAT + k0 + c4 * 8];
        }
        __syncthreads();

        #pragma unroll
        for (int kk = 0; kk < BK; kk += 16) {
            wmma::fragment<wmma::matrix_a, 16, 16, 16, half, wmma::row_major> a[4];
            wmma::fragment<wmma::matrix_b, 16, 16, 16, half, wmma::col_major> b[2];
            #pragma unroll
            for (int mi = 0; mi < 4; mi++)
                wmma::load_matrix_sync(a[mi], &As[warp_m * 64 + mi * 16][kk], LDA);
            #pragma unroll
            for (int ni = 0; ni < 2; ni++)
                wmma::load_matrix_sync(b[ni], &Bs[warp_n * 32 + ni * 16][kk], LDA);
            #pragma unroll
            for (int mi = 0; mi < 4; mi++)
                #pragma unroll
                for (int ni = 0; ni < 2; ni++)
                    wmma::mma_sync(acc[mi][ni], a[mi], b[ni], acc[mi][ni]);
        }
    }

    #pragma unroll
    for (int mi = 0; mi < 4; mi++)
        #pragma unroll
        for (int ni = 0; ni < 2; ni++)
            wmma::store_matrix_sync(
                &g_S32[(size_t)(row0 + warp_m * 64 + mi * 16) * N_ROWS +
                       (col0 + warp_n * 32 + ni * 16)],
                acc[mi][ni], N_ROWS, wmma::mem_row_major);
}

// ---------------------------------------------------------------------------
// 3. Threshold + zero-diag + rowsum + convert to fp16  (one block per row)
// ---------------------------------------------------------------------------
__global__ void rowsum_kernel() {
    const int i = blockIdx.x;
    const size_t base = (size_t)i * N_ROWS;
    float s = 0.f;
    for (int j4 = threadIdx.x; j4 < N_ROWS / 4; j4 += 256) {
        int j = j4 * 4;
        float4 v = *(const float4*)&g_S32[base + j];
        float e0 = (v.x < 1e-10f || (j + 0) == i) ? 0.f : v.x;
        float e1 = (v.y < 1e-10f || (j + 1) == i) ? 0.f : v.y;
        float e2 = (v.z < 1e-10f || (j + 2) == i) ? 0.f : v.z;
        float e3 = (v.w < 1e-10f || (j + 3) == i) ? 0.f : v.w;
        s += e0 + e1 + e2 + e3;
        __half2* dst = (__half2*)&g_Sh[base + j];
        dst[0] = __floats2half2_rn(e0, e1);
        dst[1] = __floats2half2_rn(e2, e3);
    }
    __shared__ float red[8];
    #pragma unroll
    for (int o = 16; o > 0; o >>= 1) s += __shfl_xor_sync(0xffffffff, s, o);
    if ((threadIdx.x & 31) == 0) red[threadIdx.x >> 5] = s;
    __syncthreads();
    if (threadIdx.x == 0) {
        float tot = 0.f;
        #pragma unroll
        for (int w = 0; w < 8; w++) tot += red[w];
        g_rowsum[i] = tot;
    }
}

// ---------------------------------------------------------------------------
// 4. d^-1/2, diag term, Xs = d^-1/2 * X (fp16)
// ---------------------------------------------------------------------------
__global__ void scale_kernel(const float* __restrict__ X) {
    const int i = blockIdx.x;
    float rs = g_rowsum[i] + 1.0f;
    float dinv = rsqrtf(rs);
    if (threadIdx.x == 0) {
        g_dinv[i] = dinv;
        g_dd[i] = dinv * dinv;
    }
    const float* x = X + (size_t)i * K_FEAT;
    __half* xs = g_Xs + (size_t)i * K_FEAT;
    for (int c = threadIdx.x; c < K_FEAT; c += 128) {
        xs[c] = __float2half(dinv * x[c]);
    }
}

// ---------------------------------------------------------------------------
// 5. GEMM2: Y = Sh @ Xs    (8192x8192 @ 8192x512), fp32 accum
// ---------------------------------------------------------------------------
#define LDB2 136

__global__ __launch_bounds__(256) void gemm2_kernel() {
    __shared__ __half As[BM][LDA];     // S tile: 128 rows x 32 k
    __shared__ __half Bs[BK][LDB2];    // Xs tile: 32 k x 128 cols

    const int row0 = blockIdx.y * BM;
    const int col0 = blockIdx.x * BN;   // gridDim.x = 4 over 512 cols
    const int tid  = threadIdx.x;
    const int wid  = tid >> 5;
    const int warp_m = wid >> 2;
    const int warp_n = wid & 3;

    wmma::fragment<wmma::accumulator, 16, 16, 16, float> acc[4][2];
    #pragma unroll
    for (int mi = 0; mi < 4; mi++)
        #pragma unroll
        for (int ni = 0; ni < 2; ni++)
            wmma::fill_fragment(acc[mi][ni], 0.0f);

    for (int k0 = 0; k0 < N_ROWS; k0 += BK) {
        __syncthreads();
        #pragma unroll
        for (int it = 0; it < 2; it++) {
            int idx = tid + it * 256;
            {   // A tile: 128 rows x 32 halves
                int r = idx >> 2, c4 = idx & 3;
                *(float4*)&As[r][c4 * 8] =
                    *(const float4*)&g_Sh[(size_t)(row0 + r) * N_ROWS + k0 + c4 * 8];
            }
            {   // B tile: 32 rows x 128 halves
                int r = idx >> 4, c4 = idx & 15;
                *(float4*)&Bs[r][c4 * 8] =
                    *(const float4*)&g_Xs[(size_t)(k0 + r) * K_FEAT + col0 + c4 * 8];
            }
        }
        __syncthreads();

        #pragma unroll
        for (int kk = 0; kk < BK; kk += 16) {
            wmma::fragment<wmma::matrix_a, 16, 16, 16, half, wmma::row_major> a[4];
            wmma::fragment<wmma::matrix_b, 16, 16, 16, half, wmma::row_major> b[2];
            #pragma unroll
            for (int mi = 0; mi < 4; mi++)
                wmma::load_matrix_sync(a[mi], &As[warp_m * 64 + mi * 16][kk], LDA);
            #pragma unroll
            for (int ni = 0; ni < 2; ni++)
                wmma::load_matrix_sync(b[ni], &Bs[kk][warp_n * 32 + ni * 16], LDB2);
            #pragma unroll
            for (int mi = 0; mi < 4; mi++)
                #pragma unroll
                for (int ni = 0; ni < 2; ni++)
                    wmma::mma_sync(acc[mi][ni], a[mi], b[ni], acc[mi][ni]);
        }
    }

    #pragma unroll
    for (int mi = 0; mi < 4; mi++)
        #pragma unroll
        for (int ni = 0; ni < 2; ni++)
            wmma::store_matrix_sync(
                &g_Y[(size_t)(row0 + warp_m * 64 + mi * 16) * K_FEAT +
                     (col0 + warp_n * 32 + ni * 16)],
                acc[mi][ni], K_FEAT, wmma::mem_row_major);
}

// ---------------------------------------------------------------------------
// 6. Epilogue: out = (1/3) X + (2/3) (dinv_i * Y + dd_i * X)
// ---------------------------------------------------------------------------
__global__ void epilogue_kernel(const float* __restrict__ X, float* __restrict__ out) {
    const float REG = 2.0f / 3.0f;
    int idx = blockIdx.x * 256 + threadIdx.x;
    int i = idx >> 9;   // / K_FEAT
    float x = X[idx];
    out[idx] = (1.0f - REG) * x + REG * (g_dinv[i] * g_Y[idx] + g_dd[i] * x);
}

// ---------------------------------------------------------------------------
extern "C" void kernel_launch(void* const* d_in, const int* in_sizes, int n_in,
                              void* d_out, int out_size) {
    const float* X = (const float*)d_in[0];
    float* out = (float*)d_out;

    normalize_kernel<<<N_ROWS, 128>>>(X);

    dim3 g1(N_ROWS / BN, N_ROWS / BM);   // 64 x 64 blocks
    gemm1_kernel<<<g1, 256>>>();

    rowsum_kernel<<<N_ROWS, 256>>>();
    scale_kernel<<<N_ROWS, 128>>>(X);

    dim3 g2(K_FEAT / BN, N_ROWS / BM);   // 4 x 64 blocks
    gemm2_kernel<<<g2, 256>>>();

    epilogue_kernel<<<(N_ROWS * K_FEAT) / 256, 256>>>(X, out);
}

// round 2
// speedup vs baseline: 1.2877x; 1.2877x over previous
#include <cuda_runtime.h>
#include <cuda_fp16.h>
#include <mma.h>

using namespace nvcuda;

#define N_ROWS 8192
#define K_FEAT 512
#define EPS_TH 1e-10f

static __device__ __half g_feats[(size_t)N_ROWS * K_FEAT];           // 8 MB
static __device__ __half g_Sh[(size_t)N_ROWS * N_ROWS];              // 128 MB thresholded fp16
static __device__ float  g_part[64][N_ROWS];                         // 2 MB partial row sums
static __device__ float  g_dinv[N_ROWS];
static __device__ float  g_dd[N_ROWS];
static __device__ __half g_Xs[(size_t)N_ROWS * K_FEAT];              // 8 MB
static __device__ float  g_Y[(size_t)N_ROWS * K_FEAT];               // 16 MB

// ---------------------------------------------------------------------------
// 1. Row L2-normalize X -> fp16 feats
// ---------------------------------------------------------------------------
__global__ void normalize_kernel(const float* __restrict__ X) {
    int row = blockIdx.x;
    const float* x = X + (size_t)row * K_FEAT;
    float s = 0.f;
    for (int k = threadIdx.x; k < K_FEAT; k += 128) {
        float v = x[k];
        s += v * v;
    }
    __shared__ float red[4];
    #pragma unroll
    for (int o = 16; o > 0; o >>= 1) s += __shfl_xor_sync(0xffffffff, s, o);
    if ((threadIdx.x & 31) == 0) red[threadIdx.x >> 5] = s;
    __syncthreads();
    float tot = red[0] + red[1] + red[2] + red[3];
    float inv = 1.0f / fmaxf(sqrtf(tot), 1e-12f);
    __half* f = g_feats + (size_t)row * K_FEAT;
    for (int k = threadIdx.x; k < K_FEAT; k += 128) {
        f[k] = __float2half(x[k] * inv);
    }
}

// ---------------------------------------------------------------------------
// 2. Fused GEMM1: S = feats @ feats^T, lower-triangle blocks only.
//    Epilogue: threshold + zero-diag + fp16 convert + symmetric store +
//    deterministic partial row sums (no atomics).
// ---------------------------------------------------------------------------
#define BM 128
#define BN 128
#define BK 32
#define LDA 40
#define LDT 132   // float tile leading dim (mult of 4 for wmma store)

__global__ __launch_bounds__(256) void gemm1_fused_kernel() {
    const int bx = blockIdx.x;   // column block
    const int by = blockIdx.y;   // row block
    if (bx < by) return;         // symmetric: lower/upper triangle only

    extern __shared__ char dsm[];
    __half (*As)[LDA] = (__half(*)[LDA])dsm;
    __half (*Bs)[LDA] = (__half(*)[LDA])(dsm + BM * LDA * sizeof(__half));
    float  (*Tf)[LDT] = (float(*)[LDT])dsm;   // aliased after compute

    const int row0 = by * BM;    // rows of this tile
    const int col0 = bx * BN;    // cols of this tile
    const int tid  = threadIdx.x;
    const int lane = tid & 31;
    const int wid  = tid >> 5;
    const int warp_m = wid >> 2;
    const int warp_n = wid & 3;

    wmma::fragment<wmma::accumulator, 16, 16, 16, float> acc[4][2];
    #pragma unroll
    for (int mi = 0; mi < 4; mi++)
        #pragma unroll
        for (int ni = 0; ni < 2; ni++)
            wmma::fill_fragment(acc[mi][ni], 0.0f);

    for (int k0 = 0; k0 < K_FEAT; k0 += BK) {
        __syncthreads();
        #pragma unroll
        for (int it = 0; it < 2; it++) {
            int idx = tid + it * 256;
            int r = idx >> 2, c4 = idx & 3;
            *(float4*)&As[r][c4 * 8] =
                *(const float4*)&g_feats[(size_t)(row0 + r) * K_FEAT + k0 + c4 * 8];
            *(float4*)&Bs[r][c4 * 8] =
                *(const float4*)&g_feats[(size_t)(col0 + r) * K_FEAT + k0 + c4 * 8];
        }
        __syncthreads();

        #pragma unroll
        for (int kk = 0; kk < BK; kk += 16) {
            wmma::fragment<wmma::matrix_a, 16, 16, 16, half, wmma::row_major> a[4];
            wmma::fragment<wmma::matrix_b, 16, 16, 16, half, wmma::col_major> b[2];
            #pragma unroll
            for (int mi = 0; mi < 4; mi++)
                wmma::load_matrix_sync(a[mi], &As[warp_m * 64 + mi * 16][kk], LDA);
            #pragma unroll
            for (int ni = 0; ni < 2; ni++)
                wmma::load_matrix_sync(b[ni], &Bs[warp_n * 32 + ni * 16][kk], LDA);
            #pragma unroll
            for (int mi = 0; mi < 4; mi++)
                #pragma unroll
                for (int ni = 0; ni < 2; ni++)
                    wmma::mma_sync(acc[mi][ni], a[mi], b[ni], acc[mi][ni]);
        }
    }

    // ------ epilogue ------
    __syncthreads();   // As/Bs dead; safe to alias Tf
    #pragma unroll
    for (int mi = 0; mi < 4; mi++)
        #pragma unroll
        for (int ni = 0; ni < 2; ni++)
            wmma::store_matrix_sync(
                &Tf[warp_m * 64 + mi * 16][warp_n * 32 + ni * 16],
                acc[mi][ni], LDT, wmma::mem_row_major);
    __syncthreads();

    const bool isdiag = (bx == by);

    // Direct pass: warp w handles rows w*16 .. w*16+15 of the tile.
    // Coalesced write of g_Sh[row0 + r][col0 ..], plus row-sum -> g_part[bx][row0+r]
    #pragma unroll 1
    for (int rr = 0; rr < 16; rr++) {
        int r = wid * 16 + rr;
        float4 v = *(float4*)&Tf[r][lane * 4];
        int c0 = lane * 4;
        float e0 = (v.x < EPS_TH || (isdiag && r == c0 + 0)) ? 0.f : v.x;
        float e1 = (v.y < EPS_TH || (isdiag && r == c0 + 1)) ? 0.f : v.y;
        float e2 = (v.z < EPS_TH || (isdiag && r == c0 + 2)) ? 0.f : v.z;
        float e3 = (v.w < EPS_TH || (isdiag && r == c0 + 3)) ? 0.f : v.w;
        float s = e0 + e1 + e2 + e3;
        #pragma unroll
        for (int o = 16; o > 0; o >>= 1) s += __shfl_xor_sync(0xffffffff, s, o);
        __half2* dst = (__half2*)&g_Sh[(size_t)(row0 + r) * N_ROWS + col0 + c0];
        dst[0] = __floats2half2_rn(e0, e1);
        dst[1] = __floats2half2_rn(e2, e3);
        if (lane == 0) g_part[bx][row0 + r] = s;
    }

    // Transposed pass (off-diagonal blocks): write g_Sh[col0 + c][row0 ..]
    // plus column-sum -> g_part[by][col0 + c]
    if (!isdiag) {
        #pragma unroll 1
        for (int cc = 0; cc < 16; cc++) {
            int c = wid * 16 + cc;
            float s = 0.f;
            __half h[4];
            #pragma unroll
            for (int j = 0; j < 4; j++) {
                int r = lane + 32 * j;
                float v = Tf[r][c];
                v = (v < EPS_TH) ? 0.f : v;
                s += v;
                h[j] = __float2half(v);
            }
            #pragma unroll
            for (int o = 16; o > 0; o >>= 1) s += __shfl_xor_sync(0xffffffff, s, o);
            size_t base = (size_t)(col0 + c) * N_ROWS + row0;
            #pragma unroll
            for (int j = 0; j < 4; j++)
                g_Sh[base + lane + 32 * j] = h[j];
            if (lane == 0) g_part[by][col0 + c] = s;
        }
    }
}

// ---------------------------------------------------------------------------
// 3. Reduce partials -> d^-1/2, diag term, Xs = d^-1/2 * X (fp16)
// ---------------------------------------------------------------------------
__global__ void scale_kernel(const float* __restrict__ X) {
    const int i = blockIdx.x;
    const int t = threadIdx.x;
    __shared__ float sred[2];
    __shared__ float sdinv;
    float p = (t < 64) ? g_part[t][i] : 0.f;
    #pragma unroll
    for (int o = 16; o > 0; o >>= 1) p += __shfl_xor_sync(0xffffffff, p, o);
    if (t < 64 && (t & 31) == 0) sred[t >> 5] = p;
    __syncthreads();
    if (t == 0) {
        float rs = sred[0] + sred[1] + 1.0f;
        float dinv = rsqrtf(rs);
        g_dinv[i] = dinv;
        g_dd[i] = dinv * dinv;
        sdinv = dinv;
    }
    __syncthreads();
    float dinv = sdinv;
    const float* x = X + (size_t)i * K_FEAT;
    __half* xs = g_Xs + (size_t)i * K_FEAT;
    for (int c = t; c < K_FEAT; c += 128) {
        xs[c] = __float2half(dinv * x[c]);
    }
}

// ---------------------------------------------------------------------------
// 4. GEMM2: Y = Sh @ Xs    (8192x8192 @ 8192x512), fp32 accum
// ---------------------------------------------------------------------------
#define LDB2 136

__global__ __launch_bounds__(256) void gemm2_kernel() {
    __shared__ __half As[BM][LDA];     // S tile: 128 rows x 32 k
    __shared__ __half Bs[BK][LDB2];    // Xs tile: 32 k x 128 cols

    const int row0 = blockIdx.y * BM;
    const int col0 = blockIdx.x * BN;
    const int tid  = threadIdx.x;
    const int wid  = tid >> 5;
    const int warp_m = wid >> 2;
    const int warp_n = wid & 3;

    wmma::fragment<wmma::accumulator, 16, 16, 16, float> acc[4][2];
    #pragma unroll
    for (int mi = 0; mi < 4; mi++)
        #pragma unroll
        for (int ni = 0; ni < 2; ni++)
            wmma::fill_fragment(acc[mi][ni], 0.0f);

    for (int k0 = 0; k0 < N_ROWS; k0 += BK) {
        __syncthreads();
        #pragma unroll
        for (int it = 0; it < 2; it++) {
            int idx = tid + it * 256;
            {
                int r = idx >> 2, c4 = idx & 3;
                *(float4*)&As[r][c4 * 8] =
                    *(const float4*)&g_Sh[(size_t)(row0 + r) * N_ROWS + k0 + c4 * 8];
            }
            {
                int r = idx >> 4, c4 = idx & 15;
                *(float4*)&Bs[r][c4 * 8] =
                    *(const float4*)&g_Xs[(size_t)(k0 + r) * K_FEAT + col0 + c4 * 8];
            }
        }
        __syncthreads();

        #pragma unroll
        for (int kk = 0; kk < BK; kk += 16) {
            wmma::fragment<wmma::matrix_a, 16, 16, 16, half, wmma::row_major> a[4];
            wmma::fragment<wmma::matrix_b, 16, 16, 16, half, wmma::row_major> b[2];
            #pragma unroll
            for (int mi = 0; mi < 4; mi++)
                wmma::load_matrix_sync(a[mi], &As[warp_m * 64 + mi * 16][kk], LDA);
            #pragma unroll
            for (int ni = 0; ni < 2; ni++)
                wmma::load_matrix_sync(b[ni], &Bs[kk][warp_n * 32 + ni * 16], LDB2);
            #pragma unroll
            for (int mi = 0; mi < 4; mi++)
                #pragma unroll
                for (int ni = 0; ni < 2; ni++)
                    wmma::mma_sync(acc[mi][ni], a[mi], b[ni], acc[mi][ni]);
        }
    }

    #pragma unroll
    for (int mi = 0; mi < 4; mi++)
        #pragma unroll
        for (int ni = 0; ni < 2; ni++)
            wmma::store_matrix_sync(
                &g_Y[(size_t)(row0 + warp_m * 64 + mi * 16) * K_FEAT +
                     (col0 + warp_n * 32 + ni * 16)],
                acc[mi][ni], K_FEAT, wmma::mem_row_major);
}

// ---------------------------------------------------------------------------
// 5. Epilogue: out = (1/3) X + (2/3) (dinv_i * Y + dd_i * X)
// ---------------------------------------------------------------------------
__global__ void epilogue_kernel(const float* __restrict__ X, float* __restrict__ out) {
    const float REG = 2.0f / 3.0f;
    int idx = blockIdx.x * 256 + threadIdx.x;
    int i = idx >> 9;   // / K_FEAT
    float x = X[idx];
    out[idx] = (1.0f - REG) * x + REG * (g_dinv[i] * g_Y[idx] + g_dd[i] * x);
}

// ---------------------------------------------------------------------------
extern "C" void kernel_launch(void* const* d_in, const int* in_sizes, int n_in,
                              void* d_out, int out_size) {
    const float* X = (const float*)d_in[0];
    float* out = (float*)d_out;

    const int g1_smem = BM * LDT * sizeof(float);   // 67584 B
    cudaFuncSetAttribute(gemm1_fused_kernel,
                         cudaFuncAttributeMaxDynamicSharedMemorySize, g1_smem);

    normalize_kernel<<<N_ROWS, 128>>>(X);

    dim3 g1(N_ROWS / BN, N_ROWS / BM);   // 64 x 64, lower triangle active
    gemm1_fused_kernel<<<g1, 256, g1_smem>>>();

    scale_kernel<<<N_ROWS, 128>>>(X);

    dim3 g2(K_FEAT / BN, N_ROWS / BM);   // 4 x 64
    gemm2_kernel<<<g2, 256>>>();

    epilogue_kernel<<<(N_ROWS * K_FEAT) / 256, 256>>>(X, out);
}

// round 5
// speedup vs baseline: 1.5987x; 1.2415x over previous
#include <cuda_runtime.h>
#include <cuda_fp16.h>
#include <mma.h>
#include <cstdint>

using namespace nvcuda;

#define N_ROWS 8192
#define K_FEAT 512
#define EPS_TH 1e-10f

static __device__ __half g_feats[(size_t)N_ROWS * K_FEAT];           // 8 MB
static __device__ __half g_Sh[(size_t)N_ROWS * N_ROWS];              // 128 MB thresholded fp16
static __device__ float  g_part[64][N_ROWS];                         // 2 MB partial row sums
static __device__ float  g_dinv[N_ROWS];
static __device__ float  g_dd[N_ROWS];
static __device__ __half g_Xs[(size_t)N_ROWS * K_FEAT];              // 8 MB
static __device__ float  g_Y[(size_t)N_ROWS * K_FEAT];               // 16 MB

// ---------------------------------------------------------------------------
// cp.async helpers
// ---------------------------------------------------------------------------
__device__ __forceinline__ void cp_async16(void* smem, const void* gmem) {
    unsigned int s = (unsigned int)__cvta_generic_to_shared(smem);
    asm volatile("cp.async.cg.shared.global [%0], [%1], 16;\n" :: "r"(s), "l"(gmem));
}
__device__ __forceinline__ void cp_commit() {
    asm volatile("cp.async.commit_group;\n");
}
__device__ __forceinline__ void cp_wait1() {
    asm volatile("cp.async.wait_group 1;\n");
}
__device__ __forceinline__ void cp_wait0() {
    asm volatile("cp.async.wait_group 0;\n");
}

// ---------------------------------------------------------------------------
// 1. Row L2-normalize X -> fp16 feats
// ---------------------------------------------------------------------------
__global__ void normalize_kernel(const float* __restrict__ X) {
    int row = blockIdx.x;
    const float* x = X + (size_t)row * K_FEAT;
    float s = 0.f;
    for (int k = threadIdx.x; k < K_FEAT; k += 128) {
        float v = x[k];
        s += v * v;
    }
    __shared__ float red[4];
    #pragma unroll
    for (int o = 16; o > 0; o >>= 1) s += __shfl_xor_sync(0xffffffff, s, o);
    if ((threadIdx.x & 31) == 0) red[threadIdx.x >> 5] = s;
    __syncthreads();
    float tot = red[0] + red[1] + red[2] + red[3];
    float inv = 1.0f / fmaxf(sqrtf(tot), 1e-12f);
    __half* f = g_feats + (size_t)row * K_FEAT;
    for (int k = threadIdx.x; k < K_FEAT; k += 128) {
        f[k] = __float2half(x[k] * inv);
    }
}

// ---------------------------------------------------------------------------
// 2. Fused GEMM1 (double-buffered cp.async, BK=64):
//    S = feats @ feats^T, lower-triangle blocks; epilogue thresholds,
//    zeroes diag, converts to fp16, stores both triangles, emits partial
//    row sums (deterministic slots, no atomics).
// ---------------------------------------------------------------------------
#define BM 128
#define BN 128
#define BK1 64
#define LDA1 72     // halves; 144B rows, 16B aligned
#define LDT 132     // float tile leading dim

#define G1_ABUF (BM * LDA1 * 2)            // 18432 B per buffer
#define G1_SMEM (4 * G1_ABUF)              // 73728 B total

__global__ __launch_bounds__(256) void gemm1_fused_kernel() {
    const int bx = blockIdx.x;
    const int by = blockIdx.y;
    if (bx < by) return;

    extern __shared__ char dsm[];
    float (*Tf)[LDT] = (float(*)[LDT])dsm;   // epilogue alias

    const int row0 = by * BM;
    const int col0 = bx * BN;
    const int tid  = threadIdx.x;
    const int lane = tid & 31;
    const int wid  = tid >> 5;
    const int warp_m = wid >> 2;
    const int warp_n = wid & 3;

    const int lr = tid >> 3;        // row within 32-row group
    const int lc = tid & 7;         // 16B chunk within row

    wmma::fragment<wmma::accumulator, 16, 16, 16, float> acc[4][2];
    #pragma unroll
    for (int mi = 0; mi < 4; mi++)
        #pragma unroll
        for (int ni = 0; ni < 2; ni++)
            wmma::fill_fragment(acc[mi][ni], 0.0f);

    auto As = [&](int b) { return (__half(*)[LDA1])(dsm + b * G1_ABUF); };
    auto Bs = [&](int b) { return (__half(*)[LDA1])(dsm + 2 * G1_ABUF + b * G1_ABUF); };

    auto load_stage = [&](int buf, int k0) {
        __half (*Ab)[LDA1] = As(buf);
        __half (*Bb)[LDA1] = Bs(buf);
        #pragma unroll
        for (int i = 0; i < 4; i++) {
            int r = lr + i * 32;
            cp_async16(&Ab[r][lc * 8],
                       &g_feats[(size_t)(row0 + r) * K_FEAT + k0 + lc * 8]);
            cp_async16(&Bb[r][lc * 8],
                       &g_feats[(size_t)(col0 + r) * K_FEAT + k0 + lc * 8]);
        }
        cp_commit();
    };

    const int NK = K_FEAT / BK1;   // 8
    load_stage(0, 0);

    for (int k = 0; k < NK; k++) {
        if (k + 1 < NK) { load_stage((k + 1) & 1, (k + 1) * BK1); cp_wait1(); }
        else            { cp_wait0(); }
        __syncthreads();

        __half (*Ab)[LDA1] = As(k & 1);
        __half (*Bb)[LDA1] = Bs(k & 1);
        #pragma unroll
        for (int kk = 0; kk < BK1; kk += 16) {
            wmma::fragment<wmma::matrix_a, 16, 16, 16, half, wmma::row_major> a[4];
            wmma::fragment<wmma::matrix_b, 16, 16, 16, half, wmma::col_major> b[2];
            #pragma unroll
            for (int mi = 0; mi < 4; mi++)
                wmma::load_matrix_sync(a[mi], &Ab[warp_m * 64 + mi * 16][kk], LDA1);
            #pragma unroll
            for (int ni = 0; ni < 2; ni++)
                wmma::load_matrix_sync(b[ni], &Bb[warp_n * 32 + ni * 16][kk], LDA1);
            #pragma unroll
            for (int mi = 0; mi < 4; mi++)
                #pragma unroll
                for (int ni = 0; ni < 2; ni++)
                    wmma::mma_sync(acc[mi][ni], a[mi], b[ni], acc[mi][ni]);
        }
        __syncthreads();
    }

    // ------ epilogue ------
    #pragma unroll
    for (int mi = 0; mi < 4; mi++)
        #pragma unroll
        for (int ni = 0; ni < 2; ni++)
            wmma::store_matrix_sync(
                &Tf[warp_m * 64 + mi * 16][warp_n * 32 + ni * 16],
                acc[mi][ni], LDT, wmma::mem_row_major);
    __syncthreads();

    const bool isdiag = (bx == by);

    #pragma unroll 1
    for (int rr = 0; rr < 16; rr++) {
        int r = wid * 16 + rr;
        float4 v = *(float4*)&Tf[r][lane * 4];
        int c0 = lane * 4;
        float e0 = (v.x < EPS_TH || (isdiag && r == c0 + 0)) ? 0.f : v.x;
        float e1 = (v.y < EPS_TH || (isdiag && r == c0 + 1)) ? 0.f : v.y;
        float e2 = (v.z < EPS_TH || (isdiag && r == c0 + 2)) ? 0.f : v.z;
        float e3 = (v.w < EPS_TH || (isdiag && r == c0 + 3)) ? 0.f : v.w;
        float s = e0 + e1 + e2 + e3;
        #pragma unroll
        for (int o = 16; o > 0; o >>= 1) s += __shfl_xor_sync(0xffffffff, s, o);
        __half2* dst = (__half2*)&g_Sh[(size_t)(row0 + r) * N_ROWS + col0 + c0];
        dst[0] = __floats2half2_rn(e0, e1);
        dst[1] = __floats2half2_rn(e2, e3);
        if (lane == 0) g_part[bx][row0 + r] = s;
    }

    if (!isdiag) {
        #pragma unroll 1
        for (int cc = 0; cc < 16; cc++) {
            int c = wid * 16 + cc;
            float s = 0.f;
            __half h[4];
            #pragma unroll
            for (int j = 0; j < 4; j++) {
                int r = lane + 32 * j;
                float v = Tf[r][c];
                v = (v < EPS_TH) ? 0.f : v;
                s += v;
                h[j] = __float2half(v);
            }
            #pragma unroll
            for (int o = 16; o > 0; o >>= 1) s += __shfl_xor_sync(0xffffffff, s, o);
            size_t base = (size_t)(col0 + c) * N_ROWS + row0;
            #pragma unroll
            for (int j = 0; j < 4; j++)
                g_Sh[base + lane + 32 * j] = h[j];
            if (lane == 0) g_part[by][col0 + c] = s;
        }
    }
}

// ---------------------------------------------------------------------------
// 3. Reduce partials -> d^-1/2, diag term, Xs = d^-1/2 * X (fp16)
// ---------------------------------------------------------------------------
__global__ void scale_kernel(const float* __restrict__ X) {
    const int i = blockIdx.x;
    const int t = threadIdx.x;
    __shared__ float sred[2];
    __shared__ float sdinv;
    float p = (t < 64) ? g_part[t][i] : 0.f;
    #pragma unroll
    for (int o = 16; o > 0; o >>= 1) p += __shfl_xor_sync(0xffffffff, p, o);
    if (t < 64 && (t & 31) == 0) sred[t >> 5] = p;
    __syncthreads();
    if (t == 0) {
        float rs = sred[0] + sred[1] + 1.0f;
        float dinv = rsqrtf(rs);
        g_dinv[i] = dinv;
        g_dd[i] = dinv * dinv;
        sdinv = dinv;
    }
    __syncthreads();
    float dinv = sdinv;
    const float* x = X + (size_t)i * K_FEAT;
    __half* xs = g_Xs + (size_t)i * K_FEAT;
    for (int c = t; c < K_FEAT; c += 128) {
        xs[c] = __float2half(dinv * x[c]);
    }
}

// ---------------------------------------------------------------------------
// 4. GEMM2 (double-buffered cp.async, BK=64): Y = Sh @ Xs
// ---------------------------------------------------------------------------
#define BK2 64
#define LDB2 136    // halves; 272B rows, 16B aligned

#define G2_ABUF (BM * LDA1 * 2)            // 18432 B
#define G2_BBUF (BK2 * LDB2 * 2)           // 17408 B
#define G2_SMEM (2 * G2_ABUF + 2 * G2_BBUF)  // 71680 B

__global__ __launch_bounds__(256) void gemm2_kernel() {
    extern __shared__ char dsm[];

    const int row0 = blockIdx.y * BM;
    const int col0 = blockIdx.x * BN;
    const int tid  = threadIdx.x;
    const int wid  = tid >> 5;
    const int warp_m = wid >> 2;
    const int warp_n = wid & 3;

    const int lrA = tid >> 3, lcA = tid & 7;      // A: 8 chunks/row
    const int lrB = tid >> 4, lcB = tid & 15;     // B: 16 chunks/row

    auto As = [&](int b) { return (__half(*)[LDA1])(dsm + b * G2_ABUF); };
    auto Bs = [&](int b) { return (__half(*)[LDB2])(dsm + 2 * G2_ABUF + b * G2_BBUF); };

    wmma::fragment<wmma::accumulator, 16, 16, 16, float> acc[4][2];
    #pragma unroll
    for (int mi = 0; mi < 4; mi++)
        #pragma unroll
        for (int ni = 0; ni < 2; ni++)
            wmma::fill_fragment(acc[mi][ni], 0.0f);

    auto load_stage = [&](int buf, int k0) {
        __half (*Ab)[LDA1] = As(buf);
        __half (*Bb)[LDB2] = Bs(buf);
        #pragma unroll
        for (int i = 0; i < 4; i++) {
            int r = lrA + i * 32;
            cp_async16(&Ab[r][lcA * 8],
                       &g_Sh[(size_t)(row0 + r) * N_ROWS + k0 + lcA * 8]);
        }
        #pragma unroll
        for (int i = 0; i < 4; i++) {
            int r = lrB + i * 16;
            cp_async16(&Bb[r][lcB * 8],
                       &g_Xs[(size_t)(k0 + r) * K_FEAT + col0 + lcB * 8]);
        }
        cp_commit();
    };

    const int NK = N_ROWS / BK2;   // 128
    load_stage(0, 0);

    for (int k = 0; k < NK; k++) {
        if (k + 1 < NK) { load_stage((k + 1) & 1, (k + 1) * BK2); cp_wait1(); }
        else            { cp_wait0(); }
        __syncthreads();

        __half (*Ab)[LDA1] = As(k & 1);
        __half (*Bb)[LDB2] = Bs(k & 1);
        #pragma unroll
        for (int kk = 0; kk < BK2; kk += 16) {
            wmma::fragment<wmma::matrix_a, 16, 16, 16, half, wmma::row_major> a[4];
            wmma::fragment<wmma::matrix_b, 16, 16, 16, half, wmma::row_major> b[2];
            #pragma unroll
            for (int mi = 0; mi < 4; mi++)
                wmma::load_matrix_sync(a[mi], &Ab[warp_m * 64 + mi * 16][kk], LDA1);
            #pragma unroll
            for (int ni = 0; ni < 2; ni++)
                wmma::load_matrix_sync(b[ni], &Bb[kk][warp_n * 32 + ni * 16], LDB2);
            #pragma unroll
            for (int mi = 0; mi < 4; mi++)
                #pragma unroll
                for (int ni = 0; ni < 2; ni++)
                    wmma::mma_sync(acc[mi][ni], a[mi], b[ni], acc[mi][ni]);
        }
        __syncthreads();
    }

    #pragma unroll
    for (int mi = 0; mi < 4; mi++)
        #pragma unroll
        for (int ni = 0; ni < 2; ni++)
            wmma::store_matrix_sync(
                &g_Y[(size_t)(row0 + warp_m * 64 + mi * 16) * K_FEAT +
                     (col0 + warp_n * 32 + ni * 16)],
                acc[mi][ni], K_FEAT, wmma::mem_row_major);
}

// ---------------------------------------------------------------------------
// 5. Epilogue: out = (1/3) X + (2/3) (dinv_i * Y + dd_i * X)
// ---------------------------------------------------------------------------
__global__ void epilogue_kernel(const float* __restrict__ X, float* __restrict__ out) {
    const float REG = 2.0f / 3.0f;
    int idx = blockIdx.x * 256 + threadIdx.x;
    int i = idx >> 9;
    float x = X[idx];
    out[idx] = (1.0f - REG) * x + REG * (g_dinv[i] * g_Y[idx] + g_dd[i] * x);
}

// ---------------------------------------------------------------------------
extern "C" void kernel_launch(void* const* d_in, const int* in_sizes, int n_in,
                              void* d_out, int out_size) {
    const float* X = (const float*)d_in[0];
    float* out = (float*)d_out;

    cudaFuncSetAttribute(gemm1_fused_kernel,
                         cudaFuncAttributeMaxDynamicSharedMemorySize, G1_SMEM);
    cudaFuncSetAttribute(gemm2_kernel,
                         cudaFuncAttributeMaxDynamicSharedMemorySize, G2_SMEM);

    normalize_kernel<<<N_ROWS, 128>>>(X);

    dim3 g1(N_ROWS / BN, N_ROWS / BM);   // 64 x 64, lower triangle active
    gemm1_fused_kernel<<<g1, 256, G1_SMEM>>>();

    scale_kernel<<<N_ROWS, 128>>>(X);

    dim3 g2(K_FEAT / BN, N_ROWS / BM);   // 4 x 64
    gemm2_kernel<<<g2, 256, G2_SMEM>>>();

    epilogue_kernel<<<(N_ROWS * K_FEAT) / 256, 256>>>(X, out);
}

// round 6
// speedup vs baseline: 1.6859x; 1.0546x over previous
#include <cuda_runtime.h>
#include <cuda_fp16.h>
#include <mma.h>
#include <cstdint>

using namespace nvcuda;

#define N_ROWS 8192
#define K_FEAT 512
#define EPS_TH 1e-10f
#define NSPLIT 4

static __device__ __half g_feats[(size_t)N_ROWS * K_FEAT];           // 8 MB
static __device__ __half g_Sh[(size_t)N_ROWS * N_ROWS];              // 128 MB thresholded fp16
static __device__ float  g_part[64][N_ROWS];                         // 2 MB partial row sums
static __device__ float  g_dinv[N_ROWS];
static __device__ float  g_dd[N_ROWS];
static __device__ __half g_Xs[(size_t)N_ROWS * K_FEAT];              // 8 MB
static __device__ float  g_Ypart[NSPLIT][(size_t)N_ROWS * K_FEAT];   // 64 MB

// ---------------------------------------------------------------------------
// cp.async helpers
// ---------------------------------------------------------------------------
__device__ __forceinline__ void cp_async16(void* smem, const void* gmem) {
    unsigned int s = (unsigned int)__cvta_generic_to_shared(smem);
    asm volatile("cp.async.cg.shared.global [%0], [%1], 16;\n" :: "r"(s), "l"(gmem));
}
__device__ __forceinline__ void cp_commit() {
    asm volatile("cp.async.commit_group;\n");
}
__device__ __forceinline__ void cp_wait1() {
    asm volatile("cp.async.wait_group 1;\n");
}
__device__ __forceinline__ void cp_wait0() {
    asm volatile("cp.async.wait_group 0;\n");
}

// ---------------------------------------------------------------------------
// 1. Row L2-normalize X -> fp16 feats
// ---------------------------------------------------------------------------
__global__ void normalize_kernel(const float* __restrict__ X) {
    int row = blockIdx.x;
    const float* x = X + (size_t)row * K_FEAT;
    float s = 0.f;
    for (int k = threadIdx.x; k < K_FEAT; k += 128) {
        float v = x[k];
        s += v * v;
    }
    __shared__ float red[4];
    #pragma unroll
    for (int o = 16; o > 0; o >>= 1) s += __shfl_xor_sync(0xffffffff, s, o);
    if ((threadIdx.x & 31) == 0) red[threadIdx.x >> 5] = s;
    __syncthreads();
    float tot = red[0] + red[1] + red[2] + red[3];
    float inv = 1.0f / fmaxf(sqrtf(tot), 1e-12f);
    __half* f = g_feats + (size_t)row * K_FEAT;
    for (int k = threadIdx.x; k < K_FEAT; k += 128) {
        f[k] = __float2half(x[k] * inv);
    }
}

// ---------------------------------------------------------------------------
// 2. Fused GEMM1 (double-buffered cp.async, BK=64):
//    S = feats @ feats^T, lower-triangle blocks; epilogue thresholds,
//    zeroes diag, converts to fp16, stores both triangles, emits partial
//    row sums (deterministic slots, no atomics).
// ---------------------------------------------------------------------------
#define BM 128
#define BN 128
#define BK1 64
#define LDA1 72     // halves; 144B rows, 16B aligned
#define LDT 132     // float tile leading dim

#define G1_ABUF (BM * LDA1 * 2)            // 18432 B per buffer
#define G1_SMEM (4 * G1_ABUF)              // 73728 B total

__global__ __launch_bounds__(256) void gemm1_fused_kernel() {
    const int bx = blockIdx.x;
    const int by = blockIdx.y;
    if (bx < by) return;

    extern __shared__ char dsm[];
    float (*Tf)[LDT] = (float(*)[LDT])dsm;   // epilogue alias

    const int row0 = by * BM;
    const int col0 = bx * BN;
    const int tid  = threadIdx.x;
    const int lane = tid & 31;
    const int wid  = tid >> 5;
    const int warp_m = wid >> 2;
    const int warp_n = wid & 3;

    const int lr = tid >> 3;
    const int lc = tid & 7;

    wmma::fragment<wmma::accumulator, 16, 16, 16, float> acc[4][2];
    #pragma unroll
    for (int mi = 0; mi < 4; mi++)
        #pragma unroll
        for (int ni = 0; ni < 2; ni++)
            wmma::fill_fragment(acc[mi][ni], 0.0f);

    auto As = [&](int b) { return (__half(*)[LDA1])(dsm + b * G1_ABUF); };
    auto Bs = [&](int b) { return (__half(*)[LDA1])(dsm + 2 * G1_ABUF + b * G1_ABUF); };

    auto load_stage = [&](int buf, int k0) {
        __half (*Ab)[LDA1] = As(buf);
        __half (*Bb)[LDA1] = Bs(buf);
        #pragma unroll
        for (int i = 0; i < 4; i++) {
            int r = lr + i * 32;
            cp_async16(&Ab[r][lc * 8],
                       &g_feats[(size_t)(row0 + r) * K_FEAT + k0 + lc * 8]);
            cp_async16(&Bb[r][lc * 8],
                       &g_feats[(size_t)(col0 + r) * K_FEAT + k0 + lc * 8]);
        }
        cp_commit();
    };

    const int NK = K_FEAT / BK1;   // 8
    load_stage(0, 0);

    for (int k = 0; k < NK; k++) {
        if (k + 1 < NK) { load_stage((k + 1) & 1, (k + 1) * BK1); cp_wait1(); }
        else            { cp_wait0(); }
        __syncthreads();

        __half (*Ab)[LDA1] = As(k & 1);
        __half (*Bb)[LDA1] = Bs(k & 1);
        #pragma unroll
        for (int kk = 0; kk < BK1; kk += 16) {
            wmma::fragment<wmma::matrix_a, 16, 16, 16, half, wmma::row_major> a[4];
            wmma::fragment<wmma::matrix_b, 16, 16, 16, half, wmma::col_major> b[2];
            #pragma unroll
            for (int mi = 0; mi < 4; mi++)
                wmma::load_matrix_sync(a[mi], &Ab[warp_m * 64 + mi * 16][kk], LDA1);
            #pragma unroll
            for (int ni = 0; ni < 2; ni++)
                wmma::load_matrix_sync(b[ni], &Bb[warp_n * 32 + ni * 16][kk], LDA1);
            #pragma unroll
            for (int mi = 0; mi < 4; mi++)
                #pragma unroll
                for (int ni = 0; ni < 2; ni++)
                    wmma::mma_sync(acc[mi][ni], a[mi], b[ni], acc[mi][ni]);
        }
        __syncthreads();
    }

    // ------ epilogue ------
    #pragma unroll
    for (int mi = 0; mi < 4; mi++)
        #pragma unroll
        for (int ni = 0; ni < 2; ni++)
            wmma::store_matrix_sync(
                &Tf[warp_m * 64 + mi * 16][warp_n * 32 + ni * 16],
                acc[mi][ni], LDT, wmma::mem_row_major);
    __syncthreads();

    const bool isdiag = (bx == by);

    #pragma unroll 1
    for (int rr = 0; rr < 16; rr++) {
        int r = wid * 16 + rr;
        float4 v = *(float4*)&Tf[r][lane * 4];
        int c0 = lane * 4;
        float e0 = (v.x < EPS_TH || (isdiag && r == c0 + 0)) ? 0.f : v.x;
        float e1 = (v.y < EPS_TH || (isdiag && r == c0 + 1)) ? 0.f : v.y;
        float e2 = (v.z < EPS_TH || (isdiag && r == c0 + 2)) ? 0.f : v.z;
        float e3 = (v.w < EPS_TH || (isdiag && r == c0 + 3)) ? 0.f : v.w;
        float s = e0 + e1 + e2 + e3;
        #pragma unroll
        for (int o = 16; o > 0; o >>= 1) s += __shfl_xor_sync(0xffffffff, s, o);
        __half2* dst = (__half2*)&g_Sh[(size_t)(row0 + r) * N_ROWS + col0 + c0];
        dst[0] = __floats2half2_rn(e0, e1);
        dst[1] = __floats2half2_rn(e2, e3);
        if (lane == 0) g_part[bx][row0 + r] = s;
    }

    if (!isdiag) {
        #pragma unroll 1
        for (int cc = 0; cc < 16; cc++) {
            int c = wid * 16 + cc;
            float s = 0.f;
            __half h[4];
            #pragma unroll
            for (int j = 0; j < 4; j++) {
                int r = lane + 32 * j;
                float v = Tf[r][c];
                v = (v < EPS_TH) ? 0.f : v;
                s += v;
                h[j] = __float2half(v);
            }
            #pragma unroll
            for (int o = 16; o > 0; o >>= 1) s += __shfl_xor_sync(0xffffffff, s, o);
            size_t base = (size_t)(col0 + c) * N_ROWS + row0;
            #pragma unroll
            for (int j = 0; j < 4; j++)
                g_Sh[base + lane + 32 * j] = h[j];
            if (lane == 0) g_part[by][col0 + c] = s;
        }
    }
}

// ---------------------------------------------------------------------------
// 3. Reduce partials -> d^-1/2, diag term, Xs = d^-1/2 * X (fp16)
// ---------------------------------------------------------------------------
__global__ void scale_kernel(const float* __restrict__ X) {
    const int i = blockIdx.x;
    const int t = threadIdx.x;
    __shared__ float sred[2];
    __shared__ float sdinv;
    float p = (t < 64) ? g_part[t][i] : 0.f;
    #pragma unroll
    for (int o = 16; o > 0; o >>= 1) p += __shfl_xor_sync(0xffffffff, p, o);
    if (t < 64 && (t & 31) == 0) sred[t >> 5] = p;
    __syncthreads();
    if (t == 0) {
        float rs = sred[0] + sred[1] + 1.0f;
        float dinv = rsqrtf(rs);
        g_dinv[i] = dinv;
        g_dd[i] = dinv * dinv;
        sdinv = dinv;
    }
    __syncthreads();
    float dinv = sdinv;
    const float* x = X + (size_t)i * K_FEAT;
    __half* xs = g_Xs + (size_t)i * K_FEAT;
    for (int c = t; c < K_FEAT; c += 128) {
        xs[c] = __float2half(dinv * x[c]);
    }
}

// ---------------------------------------------------------------------------
// 4. GEMM2 (split-K=4, double-buffered cp.async, BK=64):
//    Ypart[sk] = Sh[:, sk*2048:(sk+1)*2048] @ Xs[sk*2048:(sk+1)*2048, :]
// ---------------------------------------------------------------------------
#define BK2 64
#define LDB2 136    // halves; 272B rows, 16B aligned
#define KSPLIT (N_ROWS / NSPLIT)   // 2048

#define G2_ABUF (BM * LDA1 * 2)            // 18432 B
#define G2_BBUF (BK2 * LDB2 * 2)           // 17408 B
#define G2_SMEM (2 * G2_ABUF + 2 * G2_BBUF)  // 71680 B

__global__ __launch_bounds__(256) void gemm2_kernel() {
    extern __shared__ char dsm[];

    const int row0 = blockIdx.y * BM;
    const int col0 = blockIdx.x * BN;
    const int sk   = blockIdx.z;
    const int kbase = sk * KSPLIT;
    const int tid  = threadIdx.x;
    const int wid  = tid >> 5;
    const int warp_m = wid >> 2;
    const int warp_n = wid & 3;

    const int lrA = tid >> 3, lcA = tid & 7;
    const int lrB = tid >> 4, lcB = tid & 15;

    auto As = [&](int b) { return (__half(*)[LDA1])(dsm + b * G2_ABUF); };
    auto Bs = [&](int b) { return (__half(*)[LDB2])(dsm + 2 * G2_ABUF + b * G2_BBUF); };

    wmma::fragment<wmma::accumulator, 16, 16, 16, float> acc[4][2];
    #pragma unroll
    for (int mi = 0; mi < 4; mi++)
        #pragma unroll
        for (int ni = 0; ni < 2; ni++)
            wmma::fill_fragment(acc[mi][ni], 0.0f);

    auto load_stage = [&](int buf, int k0) {
        __half (*Ab)[LDA1] = As(buf);
        __half (*Bb)[LDB2] = Bs(buf);
        #pragma unroll
        for (int i = 0; i < 4; i++) {
            int r = lrA + i * 32;
            cp_async16(&Ab[r][lcA * 8],
                       &g_Sh[(size_t)(row0 + r) * N_ROWS + k0 + lcA * 8]);
        }
        #pragma unroll
        for (int i = 0; i < 4; i++) {
            int r = lrB + i * 16;
            cp_async16(&Bb[r][lcB * 8],
                       &g_Xs[(size_t)(k0 + r) * K_FEAT + col0 + lcB * 8]);
        }
        cp_commit();
    };

    const int NK = KSPLIT / BK2;   // 32
    load_stage(0, kbase);

    for (int k = 0; k < NK; k++) {
        if (k + 1 < NK) { load_stage((k + 1) & 1, kbase + (k + 1) * BK2); cp_wait1(); }
        else            { cp_wait0(); }
        __syncthreads();

        __half (*Ab)[LDA1] = As(k & 1);
        __half (*Bb)[LDB2] = Bs(k & 1);
        #pragma unroll
        for (int kk = 0; kk < BK2; kk += 16) {
            wmma::fragment<wmma::matrix_a, 16, 16, 16, half, wmma::row_major> a[4];
            wmma::fragment<wmma::matrix_b, 16, 16, 16, half, wmma::row_major> b[2];
            #pragma unroll
            for (int mi = 0; mi < 4; mi++)
                wmma::load_matrix_sync(a[mi], &Ab[warp_m * 64 + mi * 16][kk], LDA1);
            #pragma unroll
            for (int ni = 0; ni < 2; ni++)
                wmma::load_matrix_sync(b[ni], &Bb[kk][warp_n * 32 + ni * 16], LDB2);
            #pragma unroll
            for (int mi = 0; mi < 4; mi++)
                #pragma unroll
                for (int ni = 0; ni < 2; ni++)
                    wmma::mma_sync(acc[mi][ni], a[mi], b[ni], acc[mi][ni]);
        }
        __syncthreads();
    }

    float* yp = g_Ypart[sk];
    #pragma unroll
    for (int mi = 0; mi < 4; mi++)
        #pragma unroll
        for (int ni = 0; ni < 2; ni++)
            wmma::store_matrix_sync(
                &yp[(size_t)(row0 + warp_m * 64 + mi * 16) * K_FEAT +
                    (col0 + warp_n * 32 + ni * 16)],
                acc[mi][ni], K_FEAT, wmma::mem_row_major);
}

// ---------------------------------------------------------------------------
// 5. Epilogue: out = (1/3) X + (2/3) (dinv_i * sum(Ypart) + dd_i * X)
// ---------------------------------------------------------------------------
__global__ void epilogue_kernel(const float* __restrict__ X, float* __restrict__ out) {
    const float REG = 2.0f / 3.0f;
    int idx = blockIdx.x * 256 + threadIdx.x;
    int i = idx >> 9;
    float x = X[idx];
    float y = g_Ypart[0][idx] + g_Ypart[1][idx] + g_Ypart[2][idx] + g_Ypart[3][idx];
    out[idx] = (1.0f - REG) * x + REG * (g_dinv[i] * y + g_dd[i] * x);
}

// ---------------------------------------------------------------------------
extern "C" void kernel_launch(void* const* d_in, const int* in_sizes, int n_in,
                              void* d_out, int out_size) {
    const float* X = (const float*)d_in[0];
    float* out = (float*)d_out;

    cudaFuncSetAttribute(gemm1_fused_kernel,
                         cudaFuncAttributeMaxDynamicSharedMemorySize, G1_SMEM);
    cudaFuncSetAttribute(gemm2_kernel,
                         cudaFuncAttributeMaxDynamicSharedMemorySize, G2_SMEM);

    normalize_kernel<<<N_ROWS, 128>>>(X);

    dim3 g1(N_ROWS / BN, N_ROWS / BM);   // 64 x 64, lower triangle active
    gemm1_fused_kernel<<<g1, 256, G1_SMEM>>>();

    scale_kernel<<<N_ROWS, 128>>>(X);

    dim3 g2(K_FEAT / BN, N_ROWS / BM, NSPLIT);   // 4 x 64 x 4 = 1024 CTAs
    gemm2_kernel<<<g2, 256, G2_SMEM>>>();

    epilogue_kernel<<<(N_ROWS * K_FEAT) / 256, 256>>>(X, out);
}